// round 2
// baseline (speedup 1.0000x reference)
#include <cuda_runtime.h>
#include <stdint.h>

// Problem constants
#define B_  8
#define L_  4096
#define D_  1024
#define H_  16
#define DH_ 64
#define FF_ 4

constexpr int    M_ROWS = B_ * L_;                 // 32768
constexpr size_t BLD    = (size_t)M_ROWS * D_;     // 33,554,432 floats

// -------- scratch (static device globals; no allocations allowed) --------
__device__ float g_Xp [BLD];        // X + pe
__device__ float g_q  [BLD];
__device__ float g_k  [BLD];
__device__ float g_v  [BLD];
__device__ float g_ctx[BLD];        // attention output
__device__ float g_t1 [BLD];        // Wo output / FFN2 output
__device__ float g_X1 [BLD];        // after first layernorm
__device__ float g_hid[BLD * FF_];  // FFN hidden (32768 x 4096)

// ---------------------------------------------------------------------
// X + pe (pe broadcast over batch)
// ---------------------------------------------------------------------
__global__ void k_add_pe(const float* __restrict__ X,
                         const float* __restrict__ pe,
                         float* __restrict__ out) {
    size_t i = (size_t)blockIdx.x * blockDim.x + threadIdx.x;   // float4 index
    const size_t n4  = BLD / 4;
    const size_t ld4 = (size_t)L_ * D_ / 4;
    if (i >= n4) return;
    const float4 a = ((const float4*)X)[i];
    const float4 p = ((const float4*)pe)[i % ld4];
    float4 o;
    o.x = a.x + p.x; o.y = a.y + p.y; o.z = a.z + p.z; o.w = a.w + p.w;
    ((float4*)out)[i] = o;
}

// ---------------------------------------------------------------------
// SGEMM: C[M,N] = A[M,K] @ W[K,N] + bias[N], optional ReLU.
// 128x128 block tile, BK=8, 256 threads, 8x8 per thread,
// double-buffered shared memory (load next K-slice while computing).
// M % 128 == 0, N % 128 == 0, K % 8 == 0 (all shapes here comply).
// ---------------------------------------------------------------------
template<bool RELU>
__global__ __launch_bounds__(256)
void k_sgemm(const float* __restrict__ A, const float* __restrict__ W,
             const float* __restrict__ bias, float* __restrict__ C,
             int M, int N, int K) {
    __shared__ float As[2][8][128];
    __shared__ float Bs[2][8][128];

    const int tid = threadIdx.x;
    const int tx  = tid & 15;        // 0..15  -> 8 output cols each
    const int ty  = tid >> 4;        // 0..15  -> 8 output rows each

    const float* Ab = A + (size_t)blockIdx.y * 128 * K;
    const float* Wb = W + (size_t)blockIdx.x * 128;

    const int arow = tid >> 1;           // 0..127
    const int acol = (tid & 1) << 2;     // 0 or 4
    const int brow = tid >> 5;           // 0..7
    const int bcol = (tid & 31) << 2;    // 0..124

    const float* Aptr = Ab + (size_t)arow * K + acol;   // advances by +8 per stage
    const float* Bptr = Wb + (size_t)brow * N + bcol;   // advances by +8*N per stage

    float acc[8][8];
    #pragma unroll
    for (int i = 0; i < 8; i++)
        #pragma unroll
        for (int j = 0; j < 8; j++) acc[i][j] = 0.f;

    // prologue: stage 0 into buffer 0
    {
        float4 av = *(const float4*)(Aptr);
        As[0][acol + 0][arow] = av.x;
        As[0][acol + 1][arow] = av.y;
        As[0][acol + 2][arow] = av.z;
        As[0][acol + 3][arow] = av.w;
        *(float4*)(&Bs[0][brow][bcol]) = *(const float4*)(Bptr);
    }
    __syncthreads();

    const int nStages = K / 8;
    int buf = 0;
    for (int s = 0; s < nStages; s++) {
        // issue loads for next stage into the other buffer (overlap with FMAs)
        float4 av, bv;
        const bool has_next = (s + 1 < nStages);
        if (has_next) {
            av = *(const float4*)(Aptr + (s + 1) * 8);
            bv = *(const float4*)(Bptr + (size_t)(s + 1) * 8 * N);
        }

        #pragma unroll
        for (int kk = 0; kk < 8; kk++) {
            float ar[8], br[8];
            *(float4*)(ar)     = *(const float4*)(&As[buf][kk][ty * 8]);
            *(float4*)(ar + 4) = *(const float4*)(&As[buf][kk][ty * 8 + 4]);
            *(float4*)(br)     = *(const float4*)(&Bs[buf][kk][tx * 8]);
            *(float4*)(br + 4) = *(const float4*)(&Bs[buf][kk][tx * 8 + 4]);
            #pragma unroll
            for (int i = 0; i < 8; i++)
                #pragma unroll
                for (int j = 0; j < 8; j++)
                    acc[i][j] = fmaf(ar[i], br[j], acc[i][j]);
        }

        if (has_next) {
            const int nb = buf ^ 1;
            As[nb][acol + 0][arow] = av.x;
            As[nb][acol + 1][arow] = av.y;
            As[nb][acol + 2][arow] = av.z;
            As[nb][acol + 3][arow] = av.w;
            *(float4*)(&Bs[nb][brow][bcol]) = bv;
            __syncthreads();
            buf = nb;
        }
    }

    // epilogue: bias (+ReLU), vectorized stores
    const int cn = blockIdx.x * 128 + tx * 8;
    float bb[8];
    *(float4*)(bb)     = *(const float4*)(bias + cn);
    *(float4*)(bb + 4) = *(const float4*)(bias + cn + 4);

    #pragma unroll
    for (int i = 0; i < 8; i++) {
        float* Cp = C + (size_t)(blockIdx.y * 128 + ty * 8 + i) * N + cn;
        float o[8];
        #pragma unroll
        for (int j = 0; j < 8; j++) {
            float vv = acc[i][j] + bb[j];
            if (RELU) vv = fmaxf(vv, 0.f);
            o[j] = vv;
        }
        *(float4*)(Cp)     = *(const float4*)(o);
        *(float4*)(Cp + 4) = *(const float4*)(o + 4);
    }
}

// ---------------------------------------------------------------------
// Windowed attention (BELOW=1, ABOVE=1 -> window of 3).
// One warp per (b, l, h). Exactly mirrors reference semantics:
// clipped-index gather for k/v, allow = in-range && !mask[b, clipped],
// masked scores = -1e30, softmax (all-masked -> uniform 1/3).
// ---------------------------------------------------------------------
__global__ void k_attn(const float* __restrict__ q, const float* __restrict__ k,
                       const float* __restrict__ v,
                       const uint8_t* __restrict__ mask,
                       float* __restrict__ ctx) {
    const int gw   = (int)(((size_t)blockIdx.x * blockDim.x + threadIdx.x) >> 5);
    const int lane = threadIdx.x & 31;
    if (gw >= B_ * L_ * H_) return;
    const int h  = gw % H_;
    const int bl = gw / H_;           // b*L + l
    const int l  = bl % L_;
    const int b  = bl / L_;

    const float* qp = q + (size_t)bl * D_ + h * DH_;
    const float  q0 = qp[lane];
    const float  q1 = qp[lane + 32];

    float s[3], v0[3], v1[3];
    bool  allow[3];
    #pragma unroll
    for (int w = 0; w < 3; w++) {
        const int j     = l + w - 1;
        const bool vald = (j >= 0) && (j < L_);
        const int jc    = min(max(j, 0), L_ - 1);
        const size_t kr = ((size_t)b * L_ + jc) * D_ + h * DH_;
        float p = q0 * k[kr + lane] + q1 * k[kr + lane + 32];
        #pragma unroll
        for (int o = 16; o > 0; o >>= 1) p += __shfl_xor_sync(0xffffffffu, p, o);
        s[w]     = p * 0.125f;                 // / sqrt(64)
        allow[w] = vald && (mask[(size_t)b * L_ + jc] == 0);
        v0[w]    = v[kr + lane];
        v1[w]    = v[kr + lane + 32];
    }

    float sw[3], m = -1e30f;
    #pragma unroll
    for (int w = 0; w < 3; w++) { sw[w] = allow[w] ? s[w] : -1e30f; m = fmaxf(m, sw[w]); }
    float e[3], sum = 0.f;
    #pragma unroll
    for (int w = 0; w < 3; w++) { e[w] = expf(sw[w] - m); sum += e[w]; }
    const float inv = 1.f / sum;
    float o0 = 0.f, o1 = 0.f;
    #pragma unroll
    for (int w = 0; w < 3; w++) {
        const float a = e[w] * inv;
        o0 = fmaf(a, v0[w], o0);
        o1 = fmaf(a, v1[w], o1);
    }
    float* cp = ctx + (size_t)bl * D_ + h * DH_;
    cp[lane]      = o0;
    cp[lane + 32] = o1;
}

// ---------------------------------------------------------------------
// out = layernorm(A + R) * g + beta   (row length D=1024, two-pass var)
// one block (256 threads) per row, 4 elements per thread
// ---------------------------------------------------------------------
__device__ __forceinline__ float block_sum(float val, float* sbuf) {
    const int lane = threadIdx.x & 31, wid = threadIdx.x >> 5;
    #pragma unroll
    for (int o = 16; o > 0; o >>= 1) val += __shfl_xor_sync(0xffffffffu, val, o);
    if (lane == 0) sbuf[wid] = val;
    __syncthreads();
    if (wid == 0) {
        float vv = (lane < 8) ? sbuf[lane] : 0.f;
        #pragma unroll
        for (int o = 4; o > 0; o >>= 1) vv += __shfl_xor_sync(0xffffffffu, vv, o);
        if (lane == 0) sbuf[0] = vv;
    }
    __syncthreads();
    const float r = sbuf[0];
    __syncthreads();
    return r;
}

__global__ __launch_bounds__(256)
void k_add_ln(const float* __restrict__ A, const float* __restrict__ R,
              const float* __restrict__ g, const float* __restrict__ beta,
              float* __restrict__ out) {
    __shared__ float sbuf[8];
    const int row = blockIdx.x;
    const int tid = threadIdx.x;
    const size_t base = (size_t)row * D_;

    const float4 a = ((const float4*)(A + base))[tid];
    const float4 r = ((const float4*)(R + base))[tid];
    float x[4] = { a.x + r.x, a.y + r.y, a.z + r.z, a.w + r.w };

    float ps = x[0] + x[1] + x[2] + x[3];
    const float mean = block_sum(ps, sbuf) * (1.f / D_);

    float pv = 0.f;
    #pragma unroll
    for (int i = 0; i < 4; i++) { const float d = x[i] - mean; pv += d * d; }
    const float var = block_sum(pv, sbuf) * (1.f / D_);
    const float rstd = rsqrtf(var + 1e-5f);

    const float4 gg = ((const float4*)g)[tid];
    const float4 bb = ((const float4*)beta)[tid];
    float4 o;
    o.x = (x[0] - mean) * rstd * gg.x + bb.x;
    o.y = (x[1] - mean) * rstd * gg.y + bb.y;
    o.z = (x[2] - mean) * rstd * gg.z + bb.z;
    o.w = (x[3] - mean) * rstd * gg.w + bb.w;
    ((float4*)(out + base))[tid] = o;
}

// ---------------------------------------------------------------------
// Launch: all plain kernel launches on the default stream (graph-safe)
// ---------------------------------------------------------------------
extern "C" void kernel_launch(void* const* d_in, const int* in_sizes, int n_in,
                              void* d_out, int out_size) {
    const float*   X    = (const float*)d_in[0];
    const uint8_t* mask = (const uint8_t*)d_in[1];
    const float*   pe   = (const float*)d_in[2];
    const float*   Wq   = (const float*)d_in[3];
    const float*   Wk   = (const float*)d_in[4];
    const float*   Wv   = (const float*)d_in[5];
    const float*   bq   = (const float*)d_in[6];
    const float*   bk   = (const float*)d_in[7];
    const float*   bv   = (const float*)d_in[8];
    const float*   Wo   = (const float*)d_in[9];
    const float*   bo   = (const float*)d_in[10];
    const float*   g1   = (const float*)d_in[11];
    const float*   be1  = (const float*)d_in[12];
    const float*   W1   = (const float*)d_in[13];
    const float*   b1   = (const float*)d_in[14];
    const float*   W2   = (const float*)d_in[15];
    const float*   b2   = (const float*)d_in[16];
    const float*   g2   = (const float*)d_in[17];
    const float*   be2  = (const float*)d_in[18];
    float*         out  = (float*)d_out;

    float *Xp, *q, *k, *v, *ctx, *t1, *X1, *hid;
    cudaGetSymbolAddress((void**)&Xp,  g_Xp);
    cudaGetSymbolAddress((void**)&q,   g_q);
    cudaGetSymbolAddress((void**)&k,   g_k);
    cudaGetSymbolAddress((void**)&v,   g_v);
    cudaGetSymbolAddress((void**)&ctx, g_ctx);
    cudaGetSymbolAddress((void**)&t1,  g_t1);
    cudaGetSymbolAddress((void**)&X1,  g_X1);
    cudaGetSymbolAddress((void**)&hid, g_hid);

    // 1) Xp = X + pe
    {
        const size_t n4 = BLD / 4;
        k_add_pe<<<(unsigned)((n4 + 255) / 256), 256>>>(X, pe, Xp);
    }

    // 2) Q/K/V projections
    {
        dim3 grid(D_ / 128, M_ROWS / 128);
        k_sgemm<false><<<grid, 256>>>(Xp, Wq, bq, q,  M_ROWS, D_, D_);
        k_sgemm<false><<<grid, 256>>>(Xp, Wk, bk, k,  M_ROWS, D_, D_);
        k_sgemm<false><<<grid, 256>>>(Xp, Wv, bv, v,  M_ROWS, D_, D_);
    }

    // 3) window-3 attention
    {
        const int warps = B_ * L_ * H_;           // 524288
        const int blocks = warps * 32 / 256;      // 65536
        k_attn<<<blocks, 256>>>(q, k, v, mask, ctx);
    }

    // 4) output projection
    {
        dim3 grid(D_ / 128, M_ROWS / 128);
        k_sgemm<false><<<grid, 256>>>(ctx, Wo, bo, t1, M_ROWS, D_, D_);
    }

    // 5) X1 = LN(Xp + t1)
    k_add_ln<<<M_ROWS, 256>>>(Xp, t1, g1, be1, X1);

    // 6) FFN
    {
        dim3 grid1(FF_ * D_ / 128, M_ROWS / 128);
        k_sgemm<true><<<grid1, 256>>>(X1, W1, b1, hid, M_ROWS, FF_ * D_, D_);
        dim3 grid2(D_ / 128, M_ROWS / 128);
        k_sgemm<false><<<grid2, 256>>>(hid, W2, b2, t1, M_ROWS, D_, FF_ * D_);
    }

    // 7) out = LN(X1 + t1)
    k_add_ln<<<M_ROWS, 256>>>(X1, t1, g2, be2, out);
}

// round 4
// speedup vs baseline: 1.7749x; 1.7749x over previous
#include <cuda_runtime.h>
#include <stdint.h>

// Problem constants
#define B_  8
#define L_  4096
#define D_  1024
#define H_  16
#define DH_ 64
#define FF_ 4

constexpr int    M_ROWS = B_ * L_;                 // 32768
constexpr size_t BLD    = (size_t)M_ROWS * D_;     // 33,554,432 floats

// -------- scratch (static device globals; no allocations allowed) --------
__device__ float g_Xp [BLD];
__device__ float g_q  [BLD];
__device__ float g_k  [BLD];
__device__ float g_v  [BLD];
__device__ float g_ctx[BLD];
__device__ float g_t1 [BLD];
__device__ float g_X1 [BLD];
__device__ float g_hid[BLD * FF_];                 // 32768 x 4096
// transposed weights: Wt[n][k] = W[k][n]
__device__ float g_WqT[D_ * D_];
__device__ float g_WkT[D_ * D_];
__device__ float g_WvT[D_ * D_];
__device__ float g_WoT[D_ * D_];
__device__ float g_W1T[(size_t)D_ * FF_ * D_];     // [4096][1024]
__device__ float g_W2T[(size_t)FF_ * D_ * D_];     // [1024][4096]

// round fp32 -> tf32 bits (round-half-up at bit 13)
__device__ __forceinline__ float f2tf32f(float x) {
    uint32_t u = (__float_as_uint(x) + 0x1000u) & 0xFFFFE000u;
    return __uint_as_float(u);
}

__device__ __forceinline__ void mma_tf32(float* c, const uint32_t* a,
                                         uint32_t b0, uint32_t b1) {
    asm volatile(
        "mma.sync.aligned.m16n8k8.row.col.f32.tf32.tf32.f32 "
        "{%0,%1,%2,%3}, {%4,%5,%6,%7}, {%8,%9}, {%0,%1,%2,%3};\n"
        : "+f"(c[0]), "+f"(c[1]), "+f"(c[2]), "+f"(c[3])
        : "r"(a[0]), "r"(a[1]), "r"(a[2]), "r"(a[3]), "r"(b0), "r"(b1));
}

// =====================================================================
// tf32 mma.sync GEMM: C[M,N] = A[M,K] @ Bt[N,K]^T + bias, optional ReLU
// CTA tile 128x128, BK=32, 256 threads (8 warps, 4x2), warp tile 32x64.
// M,N % 128 == 0, K % 32 == 0.
// =====================================================================
constexpr int PADA = 132;        // As row pitch (floats):  [32][132]
constexpr int PADB = 36;         // Bs row pitch (floats):  [128][36]
constexpr int ASZ  = 32 * PADA;  // 4224 floats
constexpr int BSZ  = 128 * PADB; // 4608 floats
constexpr int TGEMM_SMEM = 2 * (ASZ + BSZ) * 4;    // 70656 bytes

template<bool RELU>
__global__ __launch_bounds__(256)
void k_mmagemm(const float* __restrict__ A, const float* __restrict__ Bt,
               const float* __restrict__ bias, float* __restrict__ C,
               int M, int N, int K) {
    extern __shared__ float sm[];
    float* Abuf[2] = { sm,              sm + ASZ };
    float* Bbuf[2] = { sm + 2 * ASZ,    sm + 2 * ASZ + BSZ };

    const int tid  = threadIdx.x;
    const int wid  = tid >> 5;
    const int lane = tid & 31;
    const int ar   = lane >> 2;      // 0..7
    const int ac   = lane & 3;       // 0..3
    const int wm   = (wid & 3) * 32; // warp m-offset in tile
    const int wn   = (wid >> 2) * 64;// warp n-offset in tile

    const int m0 = blockIdx.y * 128;
    const int n0 = blockIdx.x * 128;
    const float* Ag = A  + (size_t)m0 * K;
    const float* Bg = Bt + (size_t)n0 * K;

    // per-thread tile-load mapping: 4 float4 each for A and B
    // f = tid + 256*i ; row = f>>3 (0..127), c4 = f&7 -> k = c4*4
    float c[2][8][4];
    #pragma unroll
    for (int mt = 0; mt < 2; mt++)
        #pragma unroll
        for (int nt = 0; nt < 8; nt++)
            #pragma unroll
            for (int i = 0; i < 4; i++) c[mt][nt][i] = 0.f;

    // ---- prologue: stage 0 into buffer 0
    #pragma unroll
    for (int i = 0; i < 4; i++) {
        const int f = tid + 256 * i;
        const int row = f >> 3, c4 = f & 7;
        float4 av = *(const float4*)(Ag + (size_t)row * K + c4 * 4);
        float* As = Abuf[0];
        As[(c4 * 4 + 0) * PADA + row] = f2tf32f(av.x);
        As[(c4 * 4 + 1) * PADA + row] = f2tf32f(av.y);
        As[(c4 * 4 + 2) * PADA + row] = f2tf32f(av.z);
        As[(c4 * 4 + 3) * PADA + row] = f2tf32f(av.w);
        float4 bv = *(const float4*)(Bg + (size_t)row * K + c4 * 4);
        float4 bt = { f2tf32f(bv.x), f2tf32f(bv.y), f2tf32f(bv.z), f2tf32f(bv.w) };
        *(float4*)(Bbuf[0] + row * PADB + c4 * 4) = bt;
    }
    __syncthreads();

    const int nStages = K >> 5;
    int buf = 0;
    for (int s = 0; s < nStages; s++) {
        const bool has_next = (s + 1 < nStages);
        float4 sa[4], sb[4];
        if (has_next) {
            const int kb = (s + 1) << 5;
            #pragma unroll
            for (int i = 0; i < 4; i++) {
                const int f = tid + 256 * i;
                const int row = f >> 3, c4 = f & 7;
                sa[i] = *(const float4*)(Ag + (size_t)row * K + kb + c4 * 4);
                sb[i] = *(const float4*)(Bg + (size_t)row * K + kb + c4 * 4);
            }
        }

        const float* As = Abuf[buf];
        const float* Bs = Bbuf[buf];
        #pragma unroll
        for (int kk = 0; kk < 4; kk++) {
            const int k0 = kk * 8;
            uint32_t afr[2][4];
            #pragma unroll
            for (int mt = 0; mt < 2; mt++) {
                const int mb = wm + mt * 16 + ar;
                afr[mt][0] = __float_as_uint(As[(k0 + ac)     * PADA + mb]);
                afr[mt][1] = __float_as_uint(As[(k0 + ac)     * PADA + mb + 8]);
                afr[mt][2] = __float_as_uint(As[(k0 + ac + 4) * PADA + mb]);
                afr[mt][3] = __float_as_uint(As[(k0 + ac + 4) * PADA + mb + 8]);
            }
            #pragma unroll
            for (int nt = 0; nt < 8; nt++) {
                const int nb = wn + nt * 8 + ar;
                const uint32_t b0 = __float_as_uint(Bs[nb * PADB + k0 + ac]);
                const uint32_t b1 = __float_as_uint(Bs[nb * PADB + k0 + ac + 4]);
                mma_tf32(c[0][nt], afr[0], b0, b1);
                mma_tf32(c[1][nt], afr[1], b0, b1);
            }
        }

        if (has_next) {
            const int nb2 = buf ^ 1;
            float* Asn = Abuf[nb2];
            float* Bsn = Bbuf[nb2];
            #pragma unroll
            for (int i = 0; i < 4; i++) {
                const int f = tid + 256 * i;
                const int row = f >> 3, c4 = f & 7;
                Asn[(c4 * 4 + 0) * PADA + row] = f2tf32f(sa[i].x);
                Asn[(c4 * 4 + 1) * PADA + row] = f2tf32f(sa[i].y);
                Asn[(c4 * 4 + 2) * PADA + row] = f2tf32f(sa[i].z);
                Asn[(c4 * 4 + 3) * PADA + row] = f2tf32f(sa[i].w);
                float4 bt = { f2tf32f(sb[i].x), f2tf32f(sb[i].y),
                              f2tf32f(sb[i].z), f2tf32f(sb[i].w) };
                *(float4*)(Bsn + row * PADB + c4 * 4) = bt;
            }
            __syncthreads();
            buf = nb2;
        }
    }

    // ---- epilogue: bias (+ReLU), float2 stores
    #pragma unroll
    for (int nt = 0; nt < 8; nt++) {
        const int col = n0 + wn + nt * 8 + 2 * ac;
        const float2 bb = *(const float2*)(bias + col);
        #pragma unroll
        for (int mt = 0; mt < 2; mt++) {
            const int r0 = m0 + wm + mt * 16 + ar;
            float2 o0 = { c[mt][nt][0] + bb.x, c[mt][nt][1] + bb.y };
            float2 o1 = { c[mt][nt][2] + bb.x, c[mt][nt][3] + bb.y };
            if (RELU) {
                o0.x = fmaxf(o0.x, 0.f); o0.y = fmaxf(o0.y, 0.f);
                o1.x = fmaxf(o1.x, 0.f); o1.y = fmaxf(o1.y, 0.f);
            }
            *(float2*)(C + (size_t)r0 * N + col)       = o0;
            *(float2*)(C + (size_t)(r0 + 8) * N + col) = o1;
        }
    }
}

// =====================================================================
// weight transpose: Wt[n][k] = W[k][n]
// =====================================================================
__global__ void k_transpose(const float* __restrict__ W, float* __restrict__ Wt,
                            int K, int N) {
    __shared__ float t[32][33];
    const int n0 = blockIdx.x * 32, k0 = blockIdx.y * 32;
    const int tx = threadIdx.x, ty = threadIdx.y;       // (32, 8)
    #pragma unroll
    for (int j = 0; j < 32; j += 8)
        t[ty + j][tx] = W[(size_t)(k0 + ty + j) * N + n0 + tx];
    __syncthreads();
    #pragma unroll
    for (int j = 0; j < 32; j += 8)
        Wt[(size_t)(n0 + ty + j) * K + k0 + tx] = t[tx][ty + j];
}

// =====================================================================
// X + pe
// =====================================================================
__global__ void k_add_pe(const float* __restrict__ X,
                         const float* __restrict__ pe,
                         float* __restrict__ out) {
    size_t i = (size_t)blockIdx.x * blockDim.x + threadIdx.x;
    const size_t n4  = BLD / 4;
    const size_t ld4 = (size_t)L_ * D_ / 4;
    if (i >= n4) return;
    const float4 a = ((const float4*)X)[i];
    const float4 p = ((const float4*)pe)[i % ld4];
    float4 o;
    o.x = a.x + p.x; o.y = a.y + p.y; o.z = a.z + p.z; o.w = a.w + p.w;
    ((float4*)out)[i] = o;
}

// =====================================================================
// windowed attention (window 3), one warp per (b,l,h)
// =====================================================================
__global__ void k_attn(const float* __restrict__ q, const float* __restrict__ k,
                       const float* __restrict__ v,
                       const uint8_t* __restrict__ mask,
                       float* __restrict__ ctx) {
    const int gw   = (int)(((size_t)blockIdx.x * blockDim.x + threadIdx.x) >> 5);
    const int lane = threadIdx.x & 31;
    if (gw >= B_ * L_ * H_) return;
    const int h  = gw % H_;
    const int bl = gw / H_;
    const int l  = bl % L_;
    const int b  = bl / L_;

    const float* qp = q + (size_t)bl * D_ + h * DH_;
    const float  q0 = qp[lane];
    const float  q1 = qp[lane + 32];

    float s[3], v0[3], v1[3];
    bool  allow[3];
    #pragma unroll
    for (int w = 0; w < 3; w++) {
        const int j     = l + w - 1;
        const bool vald = (j >= 0) && (j < L_);
        const int jc    = min(max(j, 0), L_ - 1);
        const size_t kr = ((size_t)b * L_ + jc) * D_ + h * DH_;
        float p = q0 * k[kr + lane] + q1 * k[kr + lane + 32];
        #pragma unroll
        for (int o = 16; o > 0; o >>= 1) p += __shfl_xor_sync(0xffffffffu, p, o);
        s[w]     = p * 0.125f;
        allow[w] = vald && (mask[(size_t)b * L_ + jc] == 0);
        v0[w]    = v[kr + lane];
        v1[w]    = v[kr + lane + 32];
    }

    float sw[3], m = -1e30f;
    #pragma unroll
    for (int w = 0; w < 3; w++) { sw[w] = allow[w] ? s[w] : -1e30f; m = fmaxf(m, sw[w]); }
    float e[3], sum = 0.f;
    #pragma unroll
    for (int w = 0; w < 3; w++) { e[w] = expf(sw[w] - m); sum += e[w]; }
    const float inv = 1.f / sum;
    float o0 = 0.f, o1 = 0.f;
    #pragma unroll
    for (int w = 0; w < 3; w++) {
        const float a = e[w] * inv;
        o0 = fmaf(a, v0[w], o0);
        o1 = fmaf(a, v1[w], o1);
    }
    float* cp = ctx + (size_t)bl * D_ + h * DH_;
    cp[lane]      = o0;
    cp[lane + 32] = o1;
}

// =====================================================================
// out = layernorm(A + R) * g + beta
// =====================================================================
__device__ __forceinline__ float block_sum(float val, float* sbuf) {
    const int lane = threadIdx.x & 31, wid = threadIdx.x >> 5;
    #pragma unroll
    for (int o = 16; o > 0; o >>= 1) val += __shfl_xor_sync(0xffffffffu, val, o);
    if (lane == 0) sbuf[wid] = val;
    __syncthreads();
    if (wid == 0) {
        float vv = (lane < 8) ? sbuf[lane] : 0.f;
        #pragma unroll
        for (int o = 4; o > 0; o >>= 1) vv += __shfl_xor_sync(0xffffffffu, vv, o);
        if (lane == 0) sbuf[0] = vv;
    }
    __syncthreads();
    const float r = sbuf[0];
    __syncthreads();
    return r;
}

__global__ __launch_bounds__(256)
void k_add_ln(const float* __restrict__ A, const float* __restrict__ R,
              const float* __restrict__ g, const float* __restrict__ beta,
              float* __restrict__ out) {
    __shared__ float sbuf[8];
    const int row = blockIdx.x;
    const int tid = threadIdx.x;
    const size_t base = (size_t)row * D_;

    const float4 a = ((const float4*)(A + base))[tid];
    const float4 r = ((const float4*)(R + base))[tid];
    float x[4] = { a.x + r.x, a.y + r.y, a.z + r.z, a.w + r.w };

    float ps = x[0] + x[1] + x[2] + x[3];
    const float mean = block_sum(ps, sbuf) * (1.f / D_);

    float pv = 0.f;
    #pragma unroll
    for (int i = 0; i < 4; i++) { const float d = x[i] - mean; pv += d * d; }
    const float var = block_sum(pv, sbuf) * (1.f / D_);
    const float rstd = rsqrtf(var + 1e-5f);

    const float4 gg = ((const float4*)g)[tid];
    const float4 bb = ((const float4*)beta)[tid];
    float4 o;
    o.x = (x[0] - mean) * rstd * gg.x + bb.x;
    o.y = (x[1] - mean) * rstd * gg.y + bb.y;
    o.z = (x[2] - mean) * rstd * gg.z + bb.z;
    o.w = (x[3] - mean) * rstd * gg.w + bb.w;
    ((float4*)(out + base))[tid] = o;
}

// =====================================================================
// launch
// =====================================================================
extern "C" void kernel_launch(void* const* d_in, const int* in_sizes, int n_in,
                              void* d_out, int out_size) {
    const float*   X    = (const float*)d_in[0];
    const uint8_t* mask = (const uint8_t*)d_in[1];
    const float*   pe   = (const float*)d_in[2];
    const float*   Wq   = (const float*)d_in[3];
    const float*   Wk   = (const float*)d_in[4];
    const float*   Wv   = (const float*)d_in[5];
    const float*   bq   = (const float*)d_in[6];
    const float*   bk   = (const float*)d_in[7];
    const float*   bv   = (const float*)d_in[8];
    const float*   Wo   = (const float*)d_in[9];
    const float*   bo   = (const float*)d_in[10];
    const float*   g1   = (const float*)d_in[11];
    const float*   be1  = (const float*)d_in[12];
    const float*   W1   = (const float*)d_in[13];
    const float*   b1   = (const float*)d_in[14];
    const float*   W2   = (const float*)d_in[15];
    const float*   b2   = (const float*)d_in[16];
    const float*   g2   = (const float*)d_in[17];
    const float*   be2  = (const float*)d_in[18];
    float*         out  = (float*)d_out;

    float *Xp, *q, *k, *v, *ctx, *t1, *X1, *hid;
    float *WqT, *WkT, *WvT, *WoT, *W1T, *W2T;
    cudaGetSymbolAddress((void**)&Xp,  g_Xp);
    cudaGetSymbolAddress((void**)&q,   g_q);
    cudaGetSymbolAddress((void**)&k,   g_k);
    cudaGetSymbolAddress((void**)&v,   g_v);
    cudaGetSymbolAddress((void**)&ctx, g_ctx);
    cudaGetSymbolAddress((void**)&t1,  g_t1);
    cudaGetSymbolAddress((void**)&X1,  g_X1);
    cudaGetSymbolAddress((void**)&hid, g_hid);
    cudaGetSymbolAddress((void**)&WqT, g_WqT);
    cudaGetSymbolAddress((void**)&WkT, g_WkT);
    cudaGetSymbolAddress((void**)&WvT, g_WvT);
    cudaGetSymbolAddress((void**)&WoT, g_WoT);
    cudaGetSymbolAddress((void**)&W1T, g_W1T);
    cudaGetSymbolAddress((void**)&W2T, g_W2T);

    cudaFuncSetAttribute(k_mmagemm<false>, cudaFuncAttributeMaxDynamicSharedMemorySize, TGEMM_SMEM);
    cudaFuncSetAttribute(k_mmagemm<true>,  cudaFuncAttributeMaxDynamicSharedMemorySize, TGEMM_SMEM);

    // 0) weight transposes
    {
        dim3 blk(32, 8);
        k_transpose<<<dim3(D_ / 32, D_ / 32), blk>>>(Wq, WqT, D_, D_);
        k_transpose<<<dim3(D_ / 32, D_ / 32), blk>>>(Wk, WkT, D_, D_);
        k_transpose<<<dim3(D_ / 32, D_ / 32), blk>>>(Wv, WvT, D_, D_);
        k_transpose<<<dim3(D_ / 32, D_ / 32), blk>>>(Wo, WoT, D_, D_);
        k_transpose<<<dim3(FF_ * D_ / 32, D_ / 32), blk>>>(W1, W1T, D_, FF_ * D_);
        k_transpose<<<dim3(D_ / 32, FF_ * D_ / 32), blk>>>(W2, W2T, FF_ * D_, D_);
    }

    // 1) Xp = X + pe
    {
        const size_t n4 = BLD / 4;
        k_add_pe<<<(unsigned)((n4 + 255) / 256), 256>>>(X, pe, Xp);
    }

    // 2) QKV projections (tf32 mma.sync tensor cores)
    {
        dim3 grid(D_ / 128, M_ROWS / 128);
        k_mmagemm<false><<<grid, 256, TGEMM_SMEM>>>(Xp, WqT, bq, q, M_ROWS, D_, D_);
        k_mmagemm<false><<<grid, 256, TGEMM_SMEM>>>(Xp, WkT, bk, k, M_ROWS, D_, D_);
        k_mmagemm<false><<<grid, 256, TGEMM_SMEM>>>(Xp, WvT, bv, v, M_ROWS, D_, D_);
    }

    // 3) window-3 attention
    {
        const int warps  = B_ * L_ * H_;
        const int blocks = warps * 32 / 256;
        k_attn<<<blocks, 256>>>(q, k, v, mask, ctx);
    }

    // 4) output projection
    {
        dim3 grid(D_ / 128, M_ROWS / 128);
        k_mmagemm<false><<<grid, 256, TGEMM_SMEM>>>(ctx, WoT, bo, t1, M_ROWS, D_, D_);
    }

    // 5) X1 = LN(Xp + t1)
    k_add_ln<<<M_ROWS, 256>>>(Xp, t1, g1, be1, X1);

    // 6) FFN
    {
        dim3 grid1(FF_ * D_ / 128, M_ROWS / 128);
        k_mmagemm<true><<<grid1, 256, TGEMM_SMEM>>>(X1, W1T, b1, hid, M_ROWS, FF_ * D_, D_);
        dim3 grid2(D_ / 128, M_ROWS / 128);
        k_mmagemm<false><<<grid2, 256, TGEMM_SMEM>>>(hid, W2T, b2, t1, M_ROWS, D_, FF_ * D_);
    }

    // 7) out = LN(X1 + t1)
    k_add_ln<<<M_ROWS, 256>>>(X1, t1, g2, be2, out);
}

// round 7
// speedup vs baseline: 2.7169x; 1.5308x over previous
#include <cuda_runtime.h>
#include <stdint.h>

// Problem constants
#define B_  8
#define L_  4096
#define D_  1024
#define H_  16
#define DH_ 64
#define FF_ 4

constexpr int    M_ROWS = B_ * L_;                 // 32768
constexpr size_t BLD    = (size_t)M_ROWS * D_;     // 33,554,432 floats

// -------- scratch (static device globals; no allocations allowed) --------
__device__ float g_Xp [BLD];                       // X + pe (fp32, residual)
__device__ float g_XpR[BLD];                       // X + pe (tf32-rounded, GEMM A)
__device__ float g_q  [BLD];
__device__ float g_k  [BLD];
__device__ float g_v  [BLD];
__device__ float g_ctx[BLD];                       // attention out (tf32-rounded)
__device__ float g_t1 [BLD];
__device__ float g_X1 [BLD];                       // LN1 out fp32 (residual)
__device__ float g_X1R[BLD];                       // LN1 out tf32-rounded (GEMM A)
__device__ float g_hid[BLD * FF_];                 // FFN hidden (tf32-rounded)
// transposed + tf32-rounded weights: Wt[n][k] = round(W[k][n])
__device__ float g_WqT[D_ * D_];
__device__ float g_WkT[D_ * D_];
__device__ float g_WvT[D_ * D_];
__device__ float g_WoT[D_ * D_];
__device__ float g_W1T[(size_t)D_ * FF_ * D_];
__device__ float g_W2T[(size_t)FF_ * D_ * D_];

// round fp32 -> tf32 (round-half-up at bit 13); idempotent
__device__ __forceinline__ float f2tf32f(float x) {
    uint32_t u = (__float_as_uint(x) + 0x1000u) & 0xFFFFE000u;
    return __uint_as_float(u);
}

__device__ __forceinline__ void mma_tf32(float* c, const uint32_t* a,
                                         uint32_t b0, uint32_t b1) {
    asm volatile(
        "mma.sync.aligned.m16n8k8.row.col.f32.tf32.tf32.f32 "
        "{%0,%1,%2,%3}, {%4,%5,%6,%7}, {%8,%9}, {%0,%1,%2,%3};\n"
        : "+f"(c[0]), "+f"(c[1]), "+f"(c[2]), "+f"(c[3])
        : "r"(a[0]), "r"(a[1]), "r"(a[2]), "r"(a[3]), "r"(b0), "r"(b1));
}

// =====================================================================
// tf32 mma.sync GEMM, double-buffered static smem (LDG->reg->STS).
// C[M,N] = A[M,K] @ Bt[N,K]^T + bias, optional ReLU, optional tf32-round.
// CTA tile 128x128, BK=16, 256 threads (8 warps, 4x2), warp tile 32x64.
// SMEM tiles [row][k], pitch 20 floats -> conflict-free fragment loads.
// Inputs must already be tf32-rounded (loader copies raw bits).
// =====================================================================
constexpr int PITCH  = 20;                 // floats per tile row
constexpr int TILE_F = 128 * PITCH;        // 2560 floats per tile

template<bool RELU, bool ROUND>
__global__ __launch_bounds__(256)
void k_mmagemm(const float* __restrict__ A, const float* __restrict__ Bt,
               const float* __restrict__ bias, float* __restrict__ C,
               int M, int N, int K) {
    __shared__ float sm[2][2 * TILE_F];    // [buf][A tile | B tile] = 40960 B

    const int tid  = threadIdx.x;
    const int wid  = tid >> 5;
    const int lane = tid & 31;
    const int ar   = lane >> 2;            // 0..7
    const int ac   = lane & 3;             // 0..3
    const int wm   = (wid & 3) * 32;
    const int wn   = (wid >> 2) * 64;

    const int m0 = blockIdx.y * 128;
    const int n0 = blockIdx.x * 128;
    const float* Ag = A  + (size_t)m0 * K;
    const float* Bg = Bt + (size_t)n0 * K;

    // loader mapping: 2 float4 per operand tile per thread per stage
    const int row0 = tid >> 2,          c40 = tid & 3;         // ids 0..255
    const int row1 = (tid + 256) >> 2,  c41 = tid & 3;         // ids 256..511

    float c[2][8][4];
    #pragma unroll
    for (int mt = 0; mt < 2; mt++)
        #pragma unroll
        for (int nt = 0; nt < 8; nt++)
            #pragma unroll
            for (int i = 0; i < 4; i++) c[mt][nt][i] = 0.f;

    // ---- prologue: stage 0 -> buf 0
    {
        float4 a0 = *(const float4*)(Ag + (size_t)row0 * K + c40 * 4);
        float4 a1 = *(const float4*)(Ag + (size_t)row1 * K + c41 * 4);
        float4 b0 = *(const float4*)(Bg + (size_t)row0 * K + c40 * 4);
        float4 b1 = *(const float4*)(Bg + (size_t)row1 * K + c41 * 4);
        *(float4*)(&sm[0][row0 * PITCH + c40 * 4])          = a0;
        *(float4*)(&sm[0][row1 * PITCH + c41 * 4])          = a1;
        *(float4*)(&sm[0][TILE_F + row0 * PITCH + c40 * 4]) = b0;
        *(float4*)(&sm[0][TILE_F + row1 * PITCH + c41 * 4]) = b1;
    }
    __syncthreads();

    const int nStages = K >> 4;
    int buf = 0;
    for (int s = 0; s < nStages; s++) {
        const bool has_next = (s + 1 < nStages);
        float4 a0, a1, b0v, b1v;
        if (has_next) {
            const int kb = (s + 1) << 4;
            a0  = *(const float4*)(Ag + (size_t)row0 * K + kb + c40 * 4);
            a1  = *(const float4*)(Ag + (size_t)row1 * K + kb + c41 * 4);
            b0v = *(const float4*)(Bg + (size_t)row0 * K + kb + c40 * 4);
            b1v = *(const float4*)(Bg + (size_t)row1 * K + kb + c41 * 4);
        }

        const float* As = sm[buf];
        const float* Bs = sm[buf] + TILE_F;
        #pragma unroll
        for (int kk = 0; kk < 2; kk++) {
            const int k0 = kk * 8;
            uint32_t afr[2][4];
            #pragma unroll
            for (int mt = 0; mt < 2; mt++) {
                const int mb = wm + mt * 16 + ar;
                afr[mt][0] = __float_as_uint(As[mb * PITCH + k0 + ac]);
                afr[mt][1] = __float_as_uint(As[(mb + 8) * PITCH + k0 + ac]);
                afr[mt][2] = __float_as_uint(As[mb * PITCH + k0 + ac + 4]);
                afr[mt][3] = __float_as_uint(As[(mb + 8) * PITCH + k0 + ac + 4]);
            }
            #pragma unroll
            for (int nt = 0; nt < 8; nt++) {
                const int nb = wn + nt * 8 + ar;
                const uint32_t bb0 = __float_as_uint(Bs[nb * PITCH + k0 + ac]);
                const uint32_t bb1 = __float_as_uint(Bs[nb * PITCH + k0 + ac + 4]);
                mma_tf32(c[0][nt], afr[0], bb0, bb1);
                mma_tf32(c[1][nt], afr[1], bb0, bb1);
            }
        }

        if (has_next) {
            const int nb2 = buf ^ 1;
            *(float4*)(&sm[nb2][row0 * PITCH + c40 * 4])          = a0;
            *(float4*)(&sm[nb2][row1 * PITCH + c41 * 4])          = a1;
            *(float4*)(&sm[nb2][TILE_F + row0 * PITCH + c40 * 4]) = b0v;
            *(float4*)(&sm[nb2][TILE_F + row1 * PITCH + c41 * 4]) = b1v;
            __syncthreads();
            buf = nb2;
        }
    }

    // ---- epilogue: bias (+ReLU) (+tf32 round), float2 stores
    #pragma unroll
    for (int nt = 0; nt < 8; nt++) {
        const int col = n0 + wn + nt * 8 + 2 * ac;
        const float2 bb = *(const float2*)(bias + col);
        #pragma unroll
        for (int mt = 0; mt < 2; mt++) {
            const int r0 = m0 + wm + mt * 16 + ar;
            float2 o0 = { c[mt][nt][0] + bb.x, c[mt][nt][1] + bb.y };
            float2 o1 = { c[mt][nt][2] + bb.x, c[mt][nt][3] + bb.y };
            if (RELU) {
                o0.x = fmaxf(o0.x, 0.f); o0.y = fmaxf(o0.y, 0.f);
                o1.x = fmaxf(o1.x, 0.f); o1.y = fmaxf(o1.y, 0.f);
            }
            if (ROUND) {
                o0.x = f2tf32f(o0.x); o0.y = f2tf32f(o0.y);
                o1.x = f2tf32f(o1.x); o1.y = f2tf32f(o1.y);
            }
            *(float2*)(C + (size_t)r0 * N + col)       = o0;
            *(float2*)(C + (size_t)(r0 + 8) * N + col) = o1;
        }
    }
}

// =====================================================================
// weight transpose + tf32 round: Wt[n][k] = round(W[k][n])
// =====================================================================
__global__ void k_transpose(const float* __restrict__ W, float* __restrict__ Wt,
                            int K, int N) {
    __shared__ float t[32][33];
    const int n0 = blockIdx.x * 32, k0 = blockIdx.y * 32;
    const int tx = threadIdx.x, ty = threadIdx.y;       // (32, 8)
    #pragma unroll
    for (int j = 0; j < 32; j += 8)
        t[ty + j][tx] = W[(size_t)(k0 + ty + j) * N + n0 + tx];
    __syncthreads();
    #pragma unroll
    for (int j = 0; j < 32; j += 8)
        Wt[(size_t)(n0 + ty + j) * K + k0 + tx] = f2tf32f(t[tx][ty + j]);
}

// =====================================================================
// X + pe -> Xp (fp32) and XpR (tf32-rounded)
// =====================================================================
__global__ void k_add_pe(const float* __restrict__ X,
                         const float* __restrict__ pe,
                         float* __restrict__ outF,
                         float* __restrict__ outR) {
    size_t i = (size_t)blockIdx.x * blockDim.x + threadIdx.x;
    const size_t n4  = BLD / 4;
    const size_t ld4 = (size_t)L_ * D_ / 4;
    if (i >= n4) return;
    const float4 a = ((const float4*)X)[i];
    const float4 p = ((const float4*)pe)[i % ld4];
    float4 o;
    o.x = a.x + p.x; o.y = a.y + p.y; o.z = a.z + p.z; o.w = a.w + p.w;
    ((float4*)outF)[i] = o;
    float4 r = { f2tf32f(o.x), f2tf32f(o.y), f2tf32f(o.z), f2tf32f(o.w) };
    ((float4*)outR)[i] = r;
}

// =====================================================================
// windowed attention (window 3), one warp per (b,l,h); tf32-rounded out
// =====================================================================
__global__ void k_attn(const float* __restrict__ q, const float* __restrict__ k,
                       const float* __restrict__ v,
                       const uint8_t* __restrict__ mask,
                       float* __restrict__ ctx) {
    const int gw   = (int)(((size_t)blockIdx.x * blockDim.x + threadIdx.x) >> 5);
    const int lane = threadIdx.x & 31;
    if (gw >= B_ * L_ * H_) return;
    const int h  = gw % H_;
    const int bl = gw / H_;
    const int l  = bl % L_;
    const int b  = bl / L_;

    const float* qp = q + (size_t)bl * D_ + h * DH_;
    const float  q0 = qp[lane];
    const float  q1 = qp[lane + 32];

    float s[3], v0[3], v1[3];
    bool  allow[3];
    #pragma unroll
    for (int w = 0; w < 3; w++) {
        const int j     = l + w - 1;
        const bool vald = (j >= 0) && (j < L_);
        const int jc    = min(max(j, 0), L_ - 1);
        const size_t kr = ((size_t)b * L_ + jc) * D_ + h * DH_;
        float p = q0 * k[kr + lane] + q1 * k[kr + lane + 32];
        #pragma unroll
        for (int o = 16; o > 0; o >>= 1) p += __shfl_xor_sync(0xffffffffu, p, o);
        s[w]     = p * 0.125f;
        allow[w] = vald && (mask[(size_t)b * L_ + jc] == 0);
        v0[w]    = v[kr + lane];
        v1[w]    = v[kr + lane + 32];
    }

    float sw[3], m = -1e30f;
    #pragma unroll
    for (int w = 0; w < 3; w++) { sw[w] = allow[w] ? s[w] : -1e30f; m = fmaxf(m, sw[w]); }
    float e[3], sum = 0.f;
    #pragma unroll
    for (int w = 0; w < 3; w++) { e[w] = expf(sw[w] - m); sum += e[w]; }
    const float inv = 1.f / sum;
    float o0 = 0.f, o1 = 0.f;
    #pragma unroll
    for (int w = 0; w < 3; w++) {
        const float a = e[w] * inv;
        o0 = fmaf(a, v0[w], o0);
        o1 = fmaf(a, v1[w], o1);
    }
    float* cp = ctx + (size_t)bl * D_ + h * DH_;
    cp[lane]      = f2tf32f(o0);
    cp[lane + 32] = f2tf32f(o1);
}

// =====================================================================
// out = layernorm(A + R) * g + beta ; optional rounded second output
// =====================================================================
__device__ __forceinline__ float block_sum(float val, float* sbuf) {
    const int lane = threadIdx.x & 31, wid = threadIdx.x >> 5;
    #pragma unroll
    for (int o = 16; o > 0; o >>= 1) val += __shfl_xor_sync(0xffffffffu, val, o);
    if (lane == 0) sbuf[wid] = val;
    __syncthreads();
    if (wid == 0) {
        float vv = (lane < 8) ? sbuf[lane] : 0.f;
        #pragma unroll
        for (int o = 4; o > 0; o >>= 1) vv += __shfl_xor_sync(0xffffffffu, vv, o);
        if (lane == 0) sbuf[0] = vv;
    }
    __syncthreads();
    const float r = sbuf[0];
    __syncthreads();
    return r;
}

template<bool DUAL>
__global__ __launch_bounds__(256)
void k_add_ln(const float* __restrict__ A, const float* __restrict__ R,
              const float* __restrict__ g, const float* __restrict__ beta,
              float* __restrict__ out, float* __restrict__ outR) {
    __shared__ float sbuf[8];
    const int row = blockIdx.x;
    const int tid = threadIdx.x;
    const size_t base = (size_t)row * D_;

    const float4 a = ((const float4*)(A + base))[tid];
    const float4 r = ((const float4*)(R + base))[tid];
    float x[4] = { a.x + r.x, a.y + r.y, a.z + r.z, a.w + r.w };

    float ps = x[0] + x[1] + x[2] + x[3];
    const float mean = block_sum(ps, sbuf) * (1.f / D_);

    float pv = 0.f;
    #pragma unroll
    for (int i = 0; i < 4; i++) { const float d = x[i] - mean; pv += d * d; }
    const float var = block_sum(pv, sbuf) * (1.f / D_);
    const float rstd = rsqrtf(var + 1e-5f);

    const float4 gg = ((const float4*)g)[tid];
    const float4 bb = ((const float4*)beta)[tid];
    float4 o;
    o.x = (x[0] - mean) * rstd * gg.x + bb.x;
    o.y = (x[1] - mean) * rstd * gg.y + bb.y;
    o.z = (x[2] - mean) * rstd * gg.z + bb.z;
    o.w = (x[3] - mean) * rstd * gg.w + bb.w;
    ((float4*)(out + base))[tid] = o;
    if (DUAL) {
        float4 rr = { f2tf32f(o.x), f2tf32f(o.y), f2tf32f(o.z), f2tf32f(o.w) };
        ((float4*)(outR + base))[tid] = rr;
    }
}

// =====================================================================
// launch
// =====================================================================
extern "C" void kernel_launch(void* const* d_in, const int* in_sizes, int n_in,
                              void* d_out, int out_size) {
    const float*   X    = (const float*)d_in[0];
    const uint8_t* mask = (const uint8_t*)d_in[1];
    const float*   pe   = (const float*)d_in[2];
    const float*   Wq   = (const float*)d_in[3];
    const float*   Wk   = (const float*)d_in[4];
    const float*   Wv   = (const float*)d_in[5];
    const float*   bq   = (const float*)d_in[6];
    const float*   bk   = (const float*)d_in[7];
    const float*   bv   = (const float*)d_in[8];
    const float*   Wo   = (const float*)d_in[9];
    const float*   bo   = (const float*)d_in[10];
    const float*   g1   = (const float*)d_in[11];
    const float*   be1  = (const float*)d_in[12];
    const float*   W1   = (const float*)d_in[13];
    const float*   b1   = (const float*)d_in[14];
    const float*   W2   = (const float*)d_in[15];
    const float*   b2   = (const float*)d_in[16];
    const float*   g2   = (const float*)d_in[17];
    const float*   be2  = (const float*)d_in[18];
    float*         out  = (float*)d_out;

    float *Xp, *XpR, *q, *k, *v, *ctx, *t1, *X1, *X1R, *hid;
    float *WqT, *WkT, *WvT, *WoT, *W1T, *W2T;
    cudaGetSymbolAddress((void**)&Xp,  g_Xp);
    cudaGetSymbolAddress((void**)&XpR, g_XpR);
    cudaGetSymbolAddress((void**)&q,   g_q);
    cudaGetSymbolAddress((void**)&k,   g_k);
    cudaGetSymbolAddress((void**)&v,   g_v);
    cudaGetSymbolAddress((void**)&ctx, g_ctx);
    cudaGetSymbolAddress((void**)&t1,  g_t1);
    cudaGetSymbolAddress((void**)&X1,  g_X1);
    cudaGetSymbolAddress((void**)&X1R, g_X1R);
    cudaGetSymbolAddress((void**)&hid, g_hid);
    cudaGetSymbolAddress((void**)&WqT, g_WqT);
    cudaGetSymbolAddress((void**)&WkT, g_WkT);
    cudaGetSymbolAddress((void**)&WvT, g_WvT);
    cudaGetSymbolAddress((void**)&WoT, g_WoT);
    cudaGetSymbolAddress((void**)&W1T, g_W1T);
    cudaGetSymbolAddress((void**)&W2T, g_W2T);

    // 0) weight transposes (+ tf32 rounding)
    {
        dim3 blk(32, 8);
        k_transpose<<<dim3(D_ / 32, D_ / 32), blk>>>(Wq, WqT, D_, D_);
        k_transpose<<<dim3(D_ / 32, D_ / 32), blk>>>(Wk, WkT, D_, D_);
        k_transpose<<<dim3(D_ / 32, D_ / 32), blk>>>(Wv, WvT, D_, D_);
        k_transpose<<<dim3(D_ / 32, D_ / 32), blk>>>(Wo, WoT, D_, D_);
        k_transpose<<<dim3(FF_ * D_ / 32, D_ / 32), blk>>>(W1, W1T, D_, FF_ * D_);
        k_transpose<<<dim3(D_ / 32, FF_ * D_ / 32), blk>>>(W2, W2T, FF_ * D_, D_);
    }

    // 1) Xp = X + pe (fp32 + rounded copy)
    {
        const size_t n4 = BLD / 4;
        k_add_pe<<<(unsigned)((n4 + 255) / 256), 256>>>(X, pe, Xp, XpR);
    }

    // 2) QKV projections
    {
        dim3 grid(D_ / 128, M_ROWS / 128);
        k_mmagemm<false, false><<<grid, 256>>>(XpR, WqT, bq, q, M_ROWS, D_, D_);
        k_mmagemm<false, false><<<grid, 256>>>(XpR, WkT, bk, k, M_ROWS, D_, D_);
        k_mmagemm<false, false><<<grid, 256>>>(XpR, WvT, bv, v, M_ROWS, D_, D_);
    }

    // 3) window-3 attention (ctx tf32-rounded at store)
    {
        const int warps  = B_ * L_ * H_;
        const int blocks = warps * 32 / 256;
        k_attn<<<blocks, 256>>>(q, k, v, mask, ctx);
    }

    // 4) output projection
    {
        dim3 grid(D_ / 128, M_ROWS / 128);
        k_mmagemm<false, false><<<grid, 256>>>(ctx, WoT, bo, t1, M_ROWS, D_, D_);
    }

    // 5) X1 = LN(Xp + t1)  (fp32 + rounded copy)
    k_add_ln<true><<<M_ROWS, 256>>>(Xp, t1, g1, be1, X1, X1R);

    // 6) FFN (hidden rounded in epilogue)
    {
        dim3 grid1(FF_ * D_ / 128, M_ROWS / 128);
        k_mmagemm<true, true><<<grid1, 256>>>(X1R, W1T, b1, hid, M_ROWS, FF_ * D_, D_);
        dim3 grid2(D_ / 128, M_ROWS / 128);
        k_mmagemm<false, false><<<grid2, 256>>>(hid, W2T, b2, t1, M_ROWS, D_, FF_ * D_);
    }

    // 7) out = LN(X1 + t1)
    k_add_ln<false><<<M_ROWS, 256>>>(X1, t1, g2, be2, out, nullptr);
}